// round 16
// baseline (speedup 1.0000x reference)
#include <cuda_runtime.h>
#include <cuda_bf16.h>
#include <stdint.h>
#include <math.h>

#define N_NODES 50000
#define N_EDGES 800000
#define F 128
#define N_GRAPHS 64
#define SCAN_T 1024
#define SCAN_PER ((N_NODES + SCAN_T - 1) / SCAN_T)   // 49

#define BM 128          // GEMM rows per block
#define PITCH 136       // smem row pitch (bf16 elems)
#define GEMM_SMEM (2 * BM * PITCH * 2)   // Xs + Ws bytes (69632)

#define GATH_BLOCKS (N_NODES / 16)       // 3125, 16 nodes per block (exact)

// -------- scratch (no allocation allowed) --------
__device__ float g_dinv[N_NODES];
__device__ __nv_bfloat16 g_xwh[(size_t)N_NODES * F];  // (X@W) * dinv[row], bf16
__device__ __nv_bfloat16 g_h1h[(size_t)N_NODES * F];  // sigmoid(conv1), bf16
__device__ float g_sums[N_GRAPHS * F];
__device__ int   g_src[N_EDGES];
__device__ int   g_dst[N_EDGES];
__device__ int   g_order[N_EDGES];     // within-destination arrival order
__device__ int   g_csrc[N_EDGES];      // CSR: src per slot, grouped by dst
__device__ int   g_ideg[N_NODES];
__device__ int   g_rowptr[N_NODES + 1];
__device__ int   g_batchv[N_NODES];
__device__ int   g_is64;

__device__ __forceinline__ float sigmoidf_(float x) {
    return 1.0f / (1.0f + __expf(-x));
}

// ---------------- dtype detect (split out so scan lands in ncu slot 4) -------
__global__ void k_detect(const void* __restrict__ ei) {
    const unsigned long long* p = (const unsigned long long*)ei;
    int is64 = 1;
    for (int k = 0; k < 8; k++)
        if (p[k] >= (unsigned long long)N_NODES) is64 = 0;
    g_is64 = is64;
}

// ---------------- prep: zero ----------------
__global__ void k_prep() {
    int i = blockIdx.x * blockDim.x + threadIdx.x;
    if (i < N_NODES) g_ideg[i] = 0;
    if (i < N_GRAPHS * F) g_sums[i] = 0.0f;
}

// ----- convert edges + batch; degree histogram; record arrival order -----
__global__ void k_convert(const void* __restrict__ ei, const void* __restrict__ b) {
    int e = blockIdx.x * blockDim.x + threadIdx.x;
    int is64 = g_is64;
    if (e < N_EDGES) {
        int s, d;
        if (is64) {
            const long long* p = (const long long*)ei;
            s = (int)p[e];
            d = (int)p[e + N_EDGES];
        } else {
            const int* p = (const int*)ei;
            s = p[e];
            d = p[e + N_EDGES];
        }
        g_src[e] = s;
        g_dst[e] = d;
        g_order[e] = atomicAdd(&g_ideg[d], 1);
    }
    if (e < N_NODES) {
        if (is64) g_batchv[e] = (int)((const long long*)b)[e];
        else      g_batchv[e] = ((const int*)b)[e];
    }
}

// -------- single-block exclusive scan -> rowptr, dinv (MEASURED this round) --
__global__ void k_scan_single() {
    __shared__ int wsum[32];
    int t = threadIdx.x;
    int base = t * SCAN_PER;
    int s = 0;
    for (int i = 0; i < SCAN_PER; i++) {
        int idx = base + i;
        if (idx < N_NODES) s += g_ideg[idx];
    }
    int lane = t & 31, wid = t >> 5;
    int v = s;
    for (int o = 1; o < 32; o <<= 1) {
        int x = __shfl_up_sync(0xFFFFFFFFu, v, o);
        if (lane >= o) v += x;
    }
    if (lane == 31) wsum[wid] = v;
    __syncthreads();
    if (wid == 0) {
        int w = wsum[lane];
        for (int o = 1; o < 32; o <<= 1) {
            int x = __shfl_up_sync(0xFFFFFFFFu, w, o);
            if (lane >= o) w += x;
        }
        wsum[lane] = w;
    }
    __syncthreads();
    int run = v - s + (wid ? wsum[wid - 1] : 0);
    for (int i = 0; i < SCAN_PER; i++) {
        int idx = base + i;
        if (idx < N_NODES) {
            int d = g_ideg[idx];
            g_rowptr[idx] = run;
            g_dinv[idx] = rsqrtf(1.0f + (float)d);
            run += d;
        }
    }
    if (t == 0) g_rowptr[N_NODES] = N_EDGES;
}

// -------- fill: atomic-free (order precomputed in convert) --------
__global__ void k_fill() {
    int e = blockIdx.x * blockDim.x + threadIdx.x;
    if (e >= N_EDGES) return;
    int d = g_dst[e];
    int pos = g_rowptr[d] + g_order[e];
    g_csrc[pos] = g_src[e];
}

// ---------------- PTX helpers ----------------
__device__ __forceinline__ void ldsm_x4(unsigned int& r0, unsigned int& r1,
                                        unsigned int& r2, unsigned int& r3,
                                        unsigned int addr) {
    asm volatile("ldmatrix.sync.aligned.m8n8.x4.shared.b16 {%0,%1,%2,%3}, [%4];"
                 : "=r"(r0), "=r"(r1), "=r"(r2), "=r"(r3) : "r"(addr));
}
__device__ __forceinline__ void ldsm_x4_t(unsigned int& r0, unsigned int& r1,
                                          unsigned int& r2, unsigned int& r3,
                                          unsigned int addr) {
    asm volatile("ldmatrix.sync.aligned.m8n8.x4.trans.shared.b16 {%0,%1,%2,%3}, [%4];"
                 : "=r"(r0), "=r"(r1), "=r"(r2), "=r"(r3) : "r"(addr));
}
__device__ __forceinline__ void hmma(float* c, unsigned int a0, unsigned int a1,
                                     unsigned int a2, unsigned int a3,
                                     unsigned int b0, unsigned int b1) {
    asm volatile(
        "mma.sync.aligned.m16n8k16.row.col.f32.bf16.bf16.f32 "
        "{%0,%1,%2,%3}, {%4,%5,%6,%7}, {%8,%9}, {%0,%1,%2,%3};"
        : "+f"(c[0]), "+f"(c[1]), "+f"(c[2]), "+f"(c[3])
        : "r"(a0), "r"(a1), "r"(a2), "r"(a3), "r"(b0), "r"(b1));
}

// ------ tensor-core GEMM: g_xwh[n,:] = bf16( (X[n,:] @ W) * dinv[n] ) --------
// act == 0: X = Xext (fp32). act == 1: X = g_h1h (bf16).
__global__ void __launch_bounds__(512) k_gemm(const float* __restrict__ Xext,
                                              const float* __restrict__ W, int act) {
    extern __shared__ char sm_raw[];
    __nv_bfloat16* Xs = (__nv_bfloat16*)sm_raw;          // [BM][PITCH]
    __nv_bfloat16* Ws = Xs + BM * PITCH;                 // [128][PITCH]
    int t = threadIdx.x;                                 // 0..511
    int r0 = blockIdx.x * BM;

#pragma unroll
    for (int i = 0; i < 8; i++) {
        int idx = t + i * 512;
        int row = idx >> 5;
        int c4 = idx & 31;
        float4 w4 = reinterpret_cast<const float4*>(W)[idx];
        __nv_bfloat16* p = Ws + row * PITCH + c4 * 4;
        p[0] = __float2bfloat16(w4.x);
        p[1] = __float2bfloat16(w4.y);
        p[2] = __float2bfloat16(w4.z);
        p[3] = __float2bfloat16(w4.w);
    }
    if (act == 0) {
#pragma unroll
        for (int i = 0; i < 8; i++) {
            int idx = t + i * 512;
            int row = idx >> 5;
            int c4 = idx & 31;
            int grow = r0 + row;
            float4 v = make_float4(0.f, 0.f, 0.f, 0.f);
            if (grow < N_NODES)
                v = reinterpret_cast<const float4*>(Xext)[(size_t)grow * 32 + c4];
            __nv_bfloat16* p = Xs + row * PITCH + c4 * 4;
            p[0] = __float2bfloat16(v.x);
            p[1] = __float2bfloat16(v.y);
            p[2] = __float2bfloat16(v.z);
            p[3] = __float2bfloat16(v.w);
        }
    } else {
#pragma unroll
        for (int i = 0; i < 4; i++) {
            int idx = t + i * 512;
            int row = idx >> 4;
            int c8 = idx & 15;
            int grow = r0 + row;
            uint4 v = make_uint4(0u, 0u, 0u, 0u);
            if (grow < N_NODES)
                v = reinterpret_cast<const uint4*>(g_h1h + (size_t)grow * F)[c8];
            *reinterpret_cast<uint4*>(Xs + row * PITCH + c8 * 8) = v;
        }
    }
    __syncthreads();

    int warp = t >> 5, lane = t & 31;
    int wr = (warp >> 1) * 16;     // row slab
    int nb = (warp & 1) * 64;      // n-half

    float acc[8][4];
#pragma unroll
    for (int n = 0; n < 8; n++)
#pragma unroll
        for (int q = 0; q < 4; q++) acc[n][q] = 0.0f;

    int arow = wr + (lane & 7) + ((lane >> 3) & 1) * 8;
    int acol = (lane >> 4) * 8;
    unsigned int a_base = (unsigned int)__cvta_generic_to_shared(Xs + arow * PITCH + acol);
    int brow = (lane & 7) + ((lane >> 3) & 1) * 8;
    int bcol = (lane >> 4) * 8;
    unsigned int b_base = (unsigned int)__cvta_generic_to_shared(Ws + brow * PITCH + bcol + nb);

#pragma unroll
    for (int kt = 0; kt < 8; kt++) {
        unsigned int a0, a1, a2, a3;
        ldsm_x4(a0, a1, a2, a3, a_base + kt * 32);
#pragma unroll
        for (int np = 0; np < 4; np++) {
            unsigned int b0, b1, b2, b3;
            ldsm_x4_t(b0, b1, b2, b3,
                      b_base + kt * 16 * PITCH * 2 + np * 32);
            hmma(acc[2 * np], a0, a1, a2, a3, b0, b1);
            hmma(acc[2 * np + 1], a0, a1, a2, a3, b2, b3);
        }
    }

    int rA = r0 + wr + (lane >> 2);
    int rB = rA + 8;
    float dA = (rA < N_NODES) ? g_dinv[rA] : 0.0f;
    float dB = (rB < N_NODES) ? g_dinv[rB] : 0.0f;
#pragma unroll
    for (int nt = 0; nt < 8; nt++) {
        int c = nb + nt * 8 + (lane & 3) * 2;
        if (rA < N_NODES) {
            __nv_bfloat162 v;
            v.x = __float2bfloat16(acc[nt][0] * dA);
            v.y = __float2bfloat16(acc[nt][1] * dA);
            *reinterpret_cast<__nv_bfloat162*>(&g_xwh[(size_t)rA * F + c]) = v;
        }
        if (rB < N_NODES) {
            __nv_bfloat162 v;
            v.x = __float2bfloat16(acc[nt][2] * dB);
            v.y = __float2bfloat16(acc[nt][3] * dB);
            *reinterpret_cast<__nv_bfloat162*>(&g_xwh[(size_t)rB * F + c]) = v;
        }
    }
}

// ---- gather (R13-proven): 2 nodes/warp, lane-batched CSR indices, uint2 ----
__device__ __forceinline__ void addrow(float4& acc, uint2 u) {
    __nv_bfloat162 p0 = *reinterpret_cast<__nv_bfloat162*>(&u.x);
    __nv_bfloat162 p1 = *reinterpret_cast<__nv_bfloat162*>(&u.y);
    float2 f0 = __bfloat1622float2(p0), f1 = __bfloat1622float2(p1);
    acc.x += f0.x; acc.y += f0.y; acc.z += f1.x; acc.w += f1.y;
}
__device__ __forceinline__ uint2 ldrow(int s, int lane) {
    return reinterpret_cast<const uint2*>(g_xwh + (size_t)s * F)[lane];
}

__global__ void __launch_bounds__(256) k_gather(const float* __restrict__ bias, int act) {
    __shared__ float rows[16][F];   // 8 KB, used when act==2
    __shared__ int gs[16];
    int warp = threadIdx.x >> 5;          // 0..7
    int lane = threadIdx.x & 31;
    int nodeA = blockIdx.x * 16 + warp * 2;   // exact: 3125*16 = 50000
    int nodeB = nodeA + 1;

    if (act == 2 && threadIdx.x < 16)
        gs[threadIdx.x] = g_batchv[blockIdx.x * 16 + threadIdx.x];

    float4 accA = make_float4(0.f, 0.f, 0.f, 0.f);
    float4 accB = make_float4(0.f, 0.f, 0.f, 0.f);
    addrow(accA, ldrow(nodeA, lane));     // self-loops (pre-scaled)
    addrow(accB, ldrow(nodeB, lane));

    int beg = g_rowptr[nodeA];
    int mid = g_rowptr[nodeA + 1];
    int end = g_rowptr[nodeB + 1];

    for (int base = beg; base < end; base += 32) {
        int rem = end - base;
        int cnt = rem < 32 ? rem : 32;
        int idx = 0;
        if (base + lane < end) idx = g_csrc[base + lane];
        int j = 0;
        for (; j + 3 < cnt; j += 4) {
            int s0 = __shfl_sync(0xFFFFFFFFu, idx, j);
            int s1 = __shfl_sync(0xFFFFFFFFu, idx, j + 1);
            int s2 = __shfl_sync(0xFFFFFFFFu, idx, j + 2);
            int s3 = __shfl_sync(0xFFFFFFFFu, idx, j + 3);
            uint2 u0 = ldrow(s0, lane);
            uint2 u1 = ldrow(s1, lane);
            uint2 u2 = ldrow(s2, lane);
            uint2 u3 = ldrow(s3, lane);
            if (base + j + 0 < mid) addrow(accA, u0); else addrow(accB, u0);
            if (base + j + 1 < mid) addrow(accA, u1); else addrow(accB, u1);
            if (base + j + 2 < mid) addrow(accA, u2); else addrow(accB, u2);
            if (base + j + 3 < mid) addrow(accA, u3); else addrow(accB, u3);
        }
        for (; j < cnt; j++) {
            int s = __shfl_sync(0xFFFFFFFFu, idx, j);
            uint2 u = ldrow(s, lane);
            if (base + j < mid) addrow(accA, u); else addrow(accB, u);
        }
    }

    float dA = g_dinv[nodeA], dB = g_dinv[nodeB];
    float4 bb = reinterpret_cast<const float4*>(bias)[lane];
    float ax = bb.x + dA * accA.x, ay = bb.y + dA * accA.y;
    float az = bb.z + dA * accA.z, aw = bb.w + dA * accA.w;
    float bx = bb.x + dB * accB.x, by = bb.y + dB * accB.y;
    float bz = bb.z + dB * accB.z, bw = bb.w + dB * accB.w;

    if (act == 1) {
        ax = sigmoidf_(ax); ay = sigmoidf_(ay); az = sigmoidf_(az); aw = sigmoidf_(aw);
        bx = sigmoidf_(bx); by = sigmoidf_(by); bz = sigmoidf_(bz); bw = sigmoidf_(bw);
        __nv_bfloat162 v0, v1;
        uint2 st;
        v0.x = __float2bfloat16(ax); v0.y = __float2bfloat16(ay);
        v1.x = __float2bfloat16(az); v1.y = __float2bfloat16(aw);
        st.x = *reinterpret_cast<unsigned int*>(&v0);
        st.y = *reinterpret_cast<unsigned int*>(&v1);
        reinterpret_cast<uint2*>(g_h1h + (size_t)nodeA * F)[lane] = st;
        v0.x = __float2bfloat16(bx); v0.y = __float2bfloat16(by);
        v1.x = __float2bfloat16(bz); v1.y = __float2bfloat16(bw);
        st.x = *reinterpret_cast<unsigned int*>(&v0);
        st.y = *reinterpret_cast<unsigned int*>(&v1);
        reinterpret_cast<uint2*>(g_h1h + (size_t)nodeB * F)[lane] = st;
    } else {
        int c = lane * 4;
        rows[warp * 2][c + 0] = fmaxf(ax, 0.f);
        rows[warp * 2][c + 1] = fmaxf(ay, 0.f);
        rows[warp * 2][c + 2] = fmaxf(az, 0.f);
        rows[warp * 2][c + 3] = fmaxf(aw, 0.f);
        rows[warp * 2 + 1][c + 0] = fmaxf(bx, 0.f);
        rows[warp * 2 + 1][c + 1] = fmaxf(by, 0.f);
        rows[warp * 2 + 1][c + 2] = fmaxf(bz, 0.f);
        rows[warp * 2 + 1][c + 3] = fmaxf(bw, 0.f);
        __syncthreads();
        if (threadIdx.x < F) {
            int t = threadIdx.x;
            float acc = 0.0f;
            int curg = gs[0];
#pragma unroll
            for (int sl = 0; sl < 16; sl++) {
                int g = gs[sl];
                if (g != curg) {
                    atomicAdd(&g_sums[curg * F + t], acc);
                    acc = 0.0f;
                    curg = g;
                }
                acc += rows[sl][t];
            }
            atomicAdd(&g_sums[curg * F + t], acc);
        }
    }
}

// --------- MLP head: 4 threads per graph on layer 1, shfl-reduce ----------
__global__ void __launch_bounds__(256) k_mlp(
        const float* __restrict__ ilW, const float* __restrict__ ilb,
        const float* __restrict__ hW, const float* __restrict__ hb,
        const float* __restrict__ oW, const float* __restrict__ ob,
        float* __restrict__ out) {
    __shared__ float W1s[F * 64];
    __shared__ float W2s[64 * 16];
    __shared__ float W3s[16];
    __shared__ float b1s[64], b2s[16];
    int t = threadIdx.x;
    for (int i = t; i < F * 64; i += blockDim.x) W1s[i] = ilW[i];
    for (int i = t; i < 64 * 16; i += blockDim.x) W2s[i] = hW[i];
    if (t < 16) { W3s[t] = oW[t]; b2s[t] = hb[t]; }
    if (t < 64) b1s[t] = ilb[t];
    __syncthreads();

    int g = t >> 2;          // graph 0..63
    int q = t & 3;           // f-quarter 0..3

    int lo = 0, hi = N_NODES;
    while (lo < hi) { int m = (lo + hi) >> 1; if (g_batchv[m] < g) lo = m + 1; else hi = m; }
    int start = lo;
    lo = start; hi = N_NODES;
    while (lo < hi) { int m = (lo + hi) >> 1; if (g_batchv[m] < g + 1) lo = m + 1; else hi = m; }
    float inv = 1.0f / fmaxf((float)(lo - start), 1.0f);

    float a1[64];
#pragma unroll
    for (int j = 0; j < 64; j++) a1[j] = 0.0f;
    for (int f = q * 32; f < q * 32 + 32; f++) {
        float p = g_sums[g * F + f] * inv;
#pragma unroll
        for (int j = 0; j < 64; j++) a1[j] += p * W1s[f * 64 + j];
    }
#pragma unroll
    for (int j = 0; j < 64; j++) {
        a1[j] += __shfl_xor_sync(0xFFFFFFFFu, a1[j], 1);
        a1[j] += __shfl_xor_sync(0xFFFFFFFFu, a1[j], 2);
    }
    if (q != 0) return;

#pragma unroll
    for (int j = 0; j < 64; j++) a1[j] = sigmoidf_(a1[j] + b1s[j]);

    float a2[16];
#pragma unroll
    for (int j = 0; j < 16; j++) a2[j] = b2s[j];
    for (int f = 0; f < 64; f++) {
#pragma unroll
        for (int j = 0; j < 16; j++) a2[j] += a1[f] * W2s[f * 16 + j];
    }
    float r = ob[0];
#pragma unroll
    for (int j = 0; j < 16; j++) r += fmaxf(a2[j], 0.0f) * W3s[j];
    out[g] = r;
}

extern "C" void kernel_launch(void* const* d_in, const int* in_sizes, int n_in,
                              void* d_out, int out_size) {
    const float* x    = (const float*)d_in[0];
    const float* W1   = (const float*)d_in[1];
    const float* b1   = (const float*)d_in[2];
    const float* W2   = (const float*)d_in[3];
    const float* b2   = (const float*)d_in[4];
    const float* ilW  = (const float*)d_in[5];
    const float* ilb  = (const float*)d_in[6];
    const float* hW   = (const float*)d_in[7];
    const float* hb   = (const float*)d_in[8];
    const float* oW   = (const float*)d_in[9];
    const float* ob   = (const float*)d_in[10];
    const void*  ei    = d_in[11];
    const void*  batch = d_in[12];
    float* out = (float*)d_out;

    cudaFuncSetAttribute(k_gemm, cudaFuncAttributeMaxDynamicSharedMemorySize, GEMM_SMEM);

    const int gemm_grid = (N_NODES + BM - 1) / BM;   // 391

    k_detect<<<1, 1>>>(ei);                           // 1
    k_prep<<<(N_NODES + 255) / 256, 256>>>();         // 2
    k_convert<<<(N_EDGES + 255) / 256, 256>>>(ei, batch);  // 3
    k_scan_single<<<1, SCAN_T>>>();                   // 4: ncu slot (MEASURE)
    k_gemm<<<gemm_grid, 512, GEMM_SMEM>>>(x, W1, 0);  // 5
    k_fill<<<(N_EDGES + 255) / 256, 256>>>();         // 6
    k_gather<<<GATH_BLOCKS, 256>>>(b1, 1);            // 7: sigmoid -> bf16 h1
    k_gemm<<<gemm_grid, 512, GEMM_SMEM>>>(nullptr, W2, 1); // 8
    k_gather<<<GATH_BLOCKS, 256>>>(b2, 2);            // 9: relu + fused pool
    k_mlp<<<1, 256>>>(ilW, ilb, hW, hb, oW, ob, out); // 10
}

// round 17
// speedup vs baseline: 1.6203x; 1.6203x over previous
#include <cuda_runtime.h>
#include <cuda_bf16.h>
#include <stdint.h>
#include <math.h>

#define N_NODES 50000
#define N_EDGES 800000
#define F 128
#define N_GRAPHS 64
#define SB 256
#define NB ((N_NODES + SB - 1) / SB)     // 196

#define BM 128          // GEMM rows per block
#define PITCH 136       // smem row pitch (bf16 elems)
#define GEMM_SMEM (2 * BM * PITCH * 2)   // Xs + Ws bytes (69632)

#define GATH_BLOCKS (N_NODES / 16)       // 3125, 16 nodes per block (exact)

// -------- scratch (no allocation allowed) --------
__device__ float g_dinv[N_NODES];
__device__ __nv_bfloat16 g_xwh[(size_t)N_NODES * F];  // (X@W) * dinv[row], bf16
__device__ __nv_bfloat16 g_h1h[(size_t)N_NODES * F];  // sigmoid(conv1), bf16
__device__ float g_sums[N_GRAPHS * F];
__device__ int   g_src[N_EDGES];
__device__ int   g_dst[N_EDGES];
__device__ int   g_order[N_EDGES];     // within-destination arrival order
__device__ int   g_csrc[N_EDGES];      // CSR: src per slot, grouped by dst
__device__ int   g_ideg[N_NODES];
__device__ int   g_rowptr[N_NODES + 1];
__device__ int   g_bsum[NB];
__device__ int   g_batchv[N_NODES];
__device__ int   g_is64;

__device__ __forceinline__ float sigmoidf_(float x) {
    return 1.0f / (1.0f + __expf(-x));
}

// ---------------- prep: zero + dtype detect ----------------
__global__ void k_prep(const void* __restrict__ ei) {
    int i = blockIdx.x * blockDim.x + threadIdx.x;
    if (i < N_NODES) g_ideg[i] = 0;
    if (i < N_GRAPHS * F) g_sums[i] = 0.0f;
    if (i == 0) {
        const unsigned long long* p = (const unsigned long long*)ei;
        int is64 = 1;
        for (int k = 0; k < 8; k++)
            if (p[k] >= (unsigned long long)N_NODES) is64 = 0;
        g_is64 = is64;
    }
}

// ----- convert edges + batch; degree histogram; record arrival order -----
__global__ void k_convert(const void* __restrict__ ei, const void* __restrict__ b) {
    int e = blockIdx.x * blockDim.x + threadIdx.x;
    int is64 = g_is64;
    if (e < N_EDGES) {
        int s, d;
        if (is64) {
            const long long* p = (const long long*)ei;
            s = (int)p[e];
            d = (int)p[e + N_EDGES];
        } else {
            const int* p = (const int*)ei;
            s = p[e];
            d = p[e + N_EDGES];
        }
        g_src[e] = s;
        g_dst[e] = d;
        g_order[e] = atomicAdd(&g_ideg[d], 1);
    }
    if (e < N_NODES) {
        if (is64) g_batchv[e] = (int)((const long long*)b)[e];
        else      g_batchv[e] = ((const int*)b)[e];
    }
}

// -------- parallel scan, step 1: per-block sums (coalesced) --------
__global__ void k_scan_blocks() {
    __shared__ int sm[SB];
    int t = threadIdx.x;
    int i = blockIdx.x * SB + t;
    sm[t] = (i < N_NODES) ? g_ideg[i] : 0;
    __syncthreads();
    for (int off = SB / 2; off > 0; off >>= 1) {
        if (t < off) sm[t] += sm[t + off];
        __syncthreads();
    }
    if (t == 0) g_bsum[blockIdx.x] = sm[0];
}

// -------- parallel scan, step 2: per-block offset + intra-block scan --------
__global__ void k_scan_apply() {
    __shared__ int red[SB];
    __shared__ int sm[SB];
    int t = threadIdx.x;
    int i = blockIdx.x * SB + t;
    int v = (i < N_NODES) ? g_ideg[i] : 0;

    // block offset = sum of g_bsum[0 .. blockIdx-1]  (NB=196 < 256)
    red[t] = (t < blockIdx.x) ? g_bsum[t] : 0;
    __syncthreads();
    for (int off = SB / 2; off > 0; off >>= 1) {
        if (t < off) red[t] += red[t + off];
        __syncthreads();
    }
    int boff = red[0];

    // intra-block inclusive scan (Hillis-Steele)
    sm[t] = v;
    __syncthreads();
    for (int off = 1; off < SB; off <<= 1) {
        int x = (t >= off) ? sm[t - off] : 0;
        __syncthreads();
        sm[t] += x;
        __syncthreads();
    }
    int excl = sm[t] - v + boff;
    if (i < N_NODES) {
        g_rowptr[i] = excl;
        g_dinv[i] = rsqrtf(1.0f + (float)v);
    }
    if (i == 0) g_rowptr[N_NODES] = N_EDGES;
}

// -------- fill: atomic-free (order precomputed in convert) --------
__global__ void k_fill() {
    int e = blockIdx.x * blockDim.x + threadIdx.x;
    if (e >= N_EDGES) return;
    int d = g_dst[e];
    int pos = g_rowptr[d] + g_order[e];
    g_csrc[pos] = g_src[e];
}

// ---------------- PTX helpers ----------------
__device__ __forceinline__ void ldsm_x4(unsigned int& r0, unsigned int& r1,
                                        unsigned int& r2, unsigned int& r3,
                                        unsigned int addr) {
    asm volatile("ldmatrix.sync.aligned.m8n8.x4.shared.b16 {%0,%1,%2,%3}, [%4];"
                 : "=r"(r0), "=r"(r1), "=r"(r2), "=r"(r3) : "r"(addr));
}
__device__ __forceinline__ void ldsm_x4_t(unsigned int& r0, unsigned int& r1,
                                          unsigned int& r2, unsigned int& r3,
                                          unsigned int addr) {
    asm volatile("ldmatrix.sync.aligned.m8n8.x4.trans.shared.b16 {%0,%1,%2,%3}, [%4];"
                 : "=r"(r0), "=r"(r1), "=r"(r2), "=r"(r3) : "r"(addr));
}
__device__ __forceinline__ void hmma(float* c, unsigned int a0, unsigned int a1,
                                     unsigned int a2, unsigned int a3,
                                     unsigned int b0, unsigned int b1) {
    asm volatile(
        "mma.sync.aligned.m16n8k16.row.col.f32.bf16.bf16.f32 "
        "{%0,%1,%2,%3}, {%4,%5,%6,%7}, {%8,%9}, {%0,%1,%2,%3};"
        : "+f"(c[0]), "+f"(c[1]), "+f"(c[2]), "+f"(c[3])
        : "r"(a0), "r"(a1), "r"(a2), "r"(a3), "r"(b0), "r"(b1));
}

// ------ tensor-core GEMM: g_xwh[n,:] = bf16( (X[n,:] @ W) * dinv[n] ) --------
// act == 0: X = Xext (fp32). act == 1: X = g_h1h (bf16).
__global__ void __launch_bounds__(512) k_gemm(const float* __restrict__ Xext,
                                              const float* __restrict__ W, int act) {
    extern __shared__ char sm_raw[];
    __nv_bfloat16* Xs = (__nv_bfloat16*)sm_raw;          // [BM][PITCH]
    __nv_bfloat16* Ws = Xs + BM * PITCH;                 // [128][PITCH]
    int t = threadIdx.x;                                 // 0..511
    int r0 = blockIdx.x * BM;

#pragma unroll
    for (int i = 0; i < 8; i++) {
        int idx = t + i * 512;
        int row = idx >> 5;
        int c4 = idx & 31;
        float4 w4 = reinterpret_cast<const float4*>(W)[idx];
        __nv_bfloat16* p = Ws + row * PITCH + c4 * 4;
        p[0] = __float2bfloat16(w4.x);
        p[1] = __float2bfloat16(w4.y);
        p[2] = __float2bfloat16(w4.z);
        p[3] = __float2bfloat16(w4.w);
    }
    if (act == 0) {
#pragma unroll
        for (int i = 0; i < 8; i++) {
            int idx = t + i * 512;
            int row = idx >> 5;
            int c4 = idx & 31;
            int grow = r0 + row;
            float4 v = make_float4(0.f, 0.f, 0.f, 0.f);
            if (grow < N_NODES)
                v = reinterpret_cast<const float4*>(Xext)[(size_t)grow * 32 + c4];
            __nv_bfloat16* p = Xs + row * PITCH + c4 * 4;
            p[0] = __float2bfloat16(v.x);
            p[1] = __float2bfloat16(v.y);
            p[2] = __float2bfloat16(v.z);
            p[3] = __float2bfloat16(v.w);
        }
    } else {
#pragma unroll
        for (int i = 0; i < 4; i++) {
            int idx = t + i * 512;
            int row = idx >> 4;
            int c8 = idx & 15;
            int grow = r0 + row;
            uint4 v = make_uint4(0u, 0u, 0u, 0u);
            if (grow < N_NODES)
                v = reinterpret_cast<const uint4*>(g_h1h + (size_t)grow * F)[c8];
            *reinterpret_cast<uint4*>(Xs + row * PITCH + c8 * 8) = v;
        }
    }
    __syncthreads();

    int warp = t >> 5, lane = t & 31;
    int wr = (warp >> 1) * 16;     // row slab
    int nb = (warp & 1) * 64;      // n-half

    float acc[8][4];
#pragma unroll
    for (int n = 0; n < 8; n++)
#pragma unroll
        for (int q = 0; q < 4; q++) acc[n][q] = 0.0f;

    int arow = wr + (lane & 7) + ((lane >> 3) & 1) * 8;
    int acol = (lane >> 4) * 8;
    unsigned int a_base = (unsigned int)__cvta_generic_to_shared(Xs + arow * PITCH + acol);
    int brow = (lane & 7) + ((lane >> 3) & 1) * 8;
    int bcol = (lane >> 4) * 8;
    unsigned int b_base = (unsigned int)__cvta_generic_to_shared(Ws + brow * PITCH + bcol + nb);

#pragma unroll
    for (int kt = 0; kt < 8; kt++) {
        unsigned int a0, a1, a2, a3;
        ldsm_x4(a0, a1, a2, a3, a_base + kt * 32);
#pragma unroll
        for (int np = 0; np < 4; np++) {
            unsigned int b0, b1, b2, b3;
            ldsm_x4_t(b0, b1, b2, b3,
                      b_base + kt * 16 * PITCH * 2 + np * 32);
            hmma(acc[2 * np], a0, a1, a2, a3, b0, b1);
            hmma(acc[2 * np + 1], a0, a1, a2, a3, b2, b3);
        }
    }

    int rA = r0 + wr + (lane >> 2);
    int rB = rA + 8;
    float dA = (rA < N_NODES) ? g_dinv[rA] : 0.0f;
    float dB = (rB < N_NODES) ? g_dinv[rB] : 0.0f;
#pragma unroll
    for (int nt = 0; nt < 8; nt++) {
        int c = nb + nt * 8 + (lane & 3) * 2;
        if (rA < N_NODES) {
            __nv_bfloat162 v;
            v.x = __float2bfloat16(acc[nt][0] * dA);
            v.y = __float2bfloat16(acc[nt][1] * dA);
            *reinterpret_cast<__nv_bfloat162*>(&g_xwh[(size_t)rA * F + c]) = v;
        }
        if (rB < N_NODES) {
            __nv_bfloat162 v;
            v.x = __float2bfloat16(acc[nt][2] * dB);
            v.y = __float2bfloat16(acc[nt][3] * dB);
            *reinterpret_cast<__nv_bfloat162*>(&g_xwh[(size_t)rB * F + c]) = v;
        }
    }
}

// ---- gather (R13-proven): 2 nodes/warp, lane-batched CSR indices, uint2 ----
__device__ __forceinline__ void addrow(float4& acc, uint2 u) {
    __nv_bfloat162 p0 = *reinterpret_cast<__nv_bfloat162*>(&u.x);
    __nv_bfloat162 p1 = *reinterpret_cast<__nv_bfloat162*>(&u.y);
    float2 f0 = __bfloat1622float2(p0), f1 = __bfloat1622float2(p1);
    acc.x += f0.x; acc.y += f0.y; acc.z += f1.x; acc.w += f1.y;
}
__device__ __forceinline__ uint2 ldrow(int s, int lane) {
    return reinterpret_cast<const uint2*>(g_xwh + (size_t)s * F)[lane];
}

__global__ void __launch_bounds__(256) k_gather(const float* __restrict__ bias, int act) {
    __shared__ float rows[16][F];   // 8 KB, used when act==2
    __shared__ int gs[16];
    int warp = threadIdx.x >> 5;          // 0..7
    int lane = threadIdx.x & 31;
    int nodeA = blockIdx.x * 16 + warp * 2;   // exact: 3125*16 = 50000
    int nodeB = nodeA + 1;

    if (act == 2 && threadIdx.x < 16)
        gs[threadIdx.x] = g_batchv[blockIdx.x * 16 + threadIdx.x];

    float4 accA = make_float4(0.f, 0.f, 0.f, 0.f);
    float4 accB = make_float4(0.f, 0.f, 0.f, 0.f);
    addrow(accA, ldrow(nodeA, lane));     // self-loops (pre-scaled)
    addrow(accB, ldrow(nodeB, lane));

    int beg = g_rowptr[nodeA];
    int mid = g_rowptr[nodeA + 1];
    int end = g_rowptr[nodeB + 1];

    for (int base = beg; base < end; base += 32) {
        int rem = end - base;
        int cnt = rem < 32 ? rem : 32;
        int idx = 0;
        if (base + lane < end) idx = g_csrc[base + lane];
        int j = 0;
        for (; j + 3 < cnt; j += 4) {
            int s0 = __shfl_sync(0xFFFFFFFFu, idx, j);
            int s1 = __shfl_sync(0xFFFFFFFFu, idx, j + 1);
            int s2 = __shfl_sync(0xFFFFFFFFu, idx, j + 2);
            int s3 = __shfl_sync(0xFFFFFFFFu, idx, j + 3);
            uint2 u0 = ldrow(s0, lane);
            uint2 u1 = ldrow(s1, lane);
            uint2 u2 = ldrow(s2, lane);
            uint2 u3 = ldrow(s3, lane);
            if (base + j + 0 < mid) addrow(accA, u0); else addrow(accB, u0);
            if (base + j + 1 < mid) addrow(accA, u1); else addrow(accB, u1);
            if (base + j + 2 < mid) addrow(accA, u2); else addrow(accB, u2);
            if (base + j + 3 < mid) addrow(accA, u3); else addrow(accB, u3);
        }
        for (; j < cnt; j++) {
            int s = __shfl_sync(0xFFFFFFFFu, idx, j);
            uint2 u = ldrow(s, lane);
            if (base + j < mid) addrow(accA, u); else addrow(accB, u);
        }
    }

    float dA = g_dinv[nodeA], dB = g_dinv[nodeB];
    float4 bb = reinterpret_cast<const float4*>(bias)[lane];
    float ax = bb.x + dA * accA.x, ay = bb.y + dA * accA.y;
    float az = bb.z + dA * accA.z, aw = bb.w + dA * accA.w;
    float bx = bb.x + dB * accB.x, by = bb.y + dB * accB.y;
    float bz = bb.z + dB * accB.z, bw = bb.w + dB * accB.w;

    if (act == 1) {
        ax = sigmoidf_(ax); ay = sigmoidf_(ay); az = sigmoidf_(az); aw = sigmoidf_(aw);
        bx = sigmoidf_(bx); by = sigmoidf_(by); bz = sigmoidf_(bz); bw = sigmoidf_(bw);
        __nv_bfloat162 v0, v1;
        uint2 st;
        v0.x = __float2bfloat16(ax); v0.y = __float2bfloat16(ay);
        v1.x = __float2bfloat16(az); v1.y = __float2bfloat16(aw);
        st.x = *reinterpret_cast<unsigned int*>(&v0);
        st.y = *reinterpret_cast<unsigned int*>(&v1);
        reinterpret_cast<uint2*>(g_h1h + (size_t)nodeA * F)[lane] = st;
        v0.x = __float2bfloat16(bx); v0.y = __float2bfloat16(by);
        v1.x = __float2bfloat16(bz); v1.y = __float2bfloat16(bw);
        st.x = *reinterpret_cast<unsigned int*>(&v0);
        st.y = *reinterpret_cast<unsigned int*>(&v1);
        reinterpret_cast<uint2*>(g_h1h + (size_t)nodeB * F)[lane] = st;
    } else {
        int c = lane * 4;
        rows[warp * 2][c + 0] = fmaxf(ax, 0.f);
        rows[warp * 2][c + 1] = fmaxf(ay, 0.f);
        rows[warp * 2][c + 2] = fmaxf(az, 0.f);
        rows[warp * 2][c + 3] = fmaxf(aw, 0.f);
        rows[warp * 2 + 1][c + 0] = fmaxf(bx, 0.f);
        rows[warp * 2 + 1][c + 1] = fmaxf(by, 0.f);
        rows[warp * 2 + 1][c + 2] = fmaxf(bz, 0.f);
        rows[warp * 2 + 1][c + 3] = fmaxf(bw, 0.f);
        __syncthreads();
        if (threadIdx.x < F) {
            int t = threadIdx.x;
            float acc = 0.0f;
            int curg = gs[0];
#pragma unroll
            for (int sl = 0; sl < 16; sl++) {
                int g = gs[sl];
                if (g != curg) {
                    atomicAdd(&g_sums[curg * F + t], acc);
                    acc = 0.0f;
                    curg = g;
                }
                acc += rows[sl][t];
            }
            atomicAdd(&g_sums[curg * F + t], acc);
        }
    }
}

// ---------------- MLP head (R13-proven serial version) ----------------
__global__ void k_mlp(const float* __restrict__ ilW, const float* __restrict__ ilb,
                      const float* __restrict__ hW, const float* __restrict__ hb,
                      const float* __restrict__ oW, const float* __restrict__ ob,
                      float* __restrict__ out) {
    __shared__ float W1s[F * 64];
    __shared__ float W2s[64 * 16];
    __shared__ float W3s[16];
    __shared__ float b1s[64], b2s[16];
    int t = threadIdx.x;
    for (int i = t; i < F * 64; i += blockDim.x) W1s[i] = ilW[i];
    for (int i = t; i < 64 * 16; i += blockDim.x) W2s[i] = hW[i];
    if (t < 16) { W3s[t] = oW[t]; b2s[t] = hb[t]; }
    if (t < 64) b1s[t] = ilb[t];
    __syncthreads();

    if (t >= N_GRAPHS) return;

    int lo = 0, hi = N_NODES;
    while (lo < hi) { int m = (lo + hi) >> 1; if (g_batchv[m] < t) lo = m + 1; else hi = m; }
    int start = lo;
    lo = start; hi = N_NODES;
    while (lo < hi) { int m = (lo + hi) >> 1; if (g_batchv[m] < t + 1) lo = m + 1; else hi = m; }
    float inv = 1.0f / fmaxf((float)(lo - start), 1.0f);

    float a1[64];
#pragma unroll
    for (int j = 0; j < 64; j++) a1[j] = b1s[j];
    for (int f = 0; f < F; f++) {
        float p = g_sums[t * F + f] * inv;
#pragma unroll
        for (int j = 0; j < 64; j++) a1[j] += p * W1s[f * 64 + j];
    }
#pragma unroll
    for (int j = 0; j < 64; j++) a1[j] = sigmoidf_(a1[j]);

    float a2[16];
#pragma unroll
    for (int j = 0; j < 16; j++) a2[j] = b2s[j];
    for (int f = 0; f < 64; f++) {
#pragma unroll
        for (int j = 0; j < 16; j++) a2[j] += a1[f] * W2s[f * 16 + j];
    }
    float r = ob[0];
#pragma unroll
    for (int j = 0; j < 16; j++) r += fmaxf(a2[j], 0.0f) * W3s[j];
    out[t] = r;
}

extern "C" void kernel_launch(void* const* d_in, const int* in_sizes, int n_in,
                              void* d_out, int out_size) {
    const float* x    = (const float*)d_in[0];
    const float* W1   = (const float*)d_in[1];
    const float* b1   = (const float*)d_in[2];
    const float* W2   = (const float*)d_in[3];
    const float* b2   = (const float*)d_in[4];
    const float* ilW  = (const float*)d_in[5];
    const float* ilb  = (const float*)d_in[6];
    const float* hW   = (const float*)d_in[7];
    const float* hb   = (const float*)d_in[8];
    const float* oW   = (const float*)d_in[9];
    const float* ob   = (const float*)d_in[10];
    const void*  ei    = d_in[11];
    const void*  batch = d_in[12];
    float* out = (float*)d_out;

    cudaFuncSetAttribute(k_gemm, cudaFuncAttributeMaxDynamicSharedMemorySize, GEMM_SMEM);

    const int gemm_grid = (N_NODES + BM - 1) / BM;   // 391

    k_prep<<<NB, SB>>>(ei);                                // 1
    k_convert<<<(N_EDGES + 255) / 256, 256>>>(ei, batch);  // 2
    k_scan_blocks<<<NB, SB>>>();                           // 3
    k_scan_apply<<<NB, SB>>>();                            // 4: ncu slot
    k_gemm<<<gemm_grid, 512, GEMM_SMEM>>>(x, W1, 0);       // 5
    k_fill<<<(N_EDGES + 255) / 256, 256>>>();              // 6
    k_gather<<<GATH_BLOCKS, 256>>>(b1, 1);                 // 7: sigmoid -> h1
    k_gemm<<<gemm_grid, 512, GEMM_SMEM>>>(nullptr, W2, 1); // 8
    k_gather<<<GATH_BLOCKS, 256>>>(b2, 2);                 // 9: relu + pool
    k_mlp<<<1, 256>>>(ilW, ilb, hW, hb, oW, ob, out);      // 10
}